// round 5
// baseline (speedup 1.0000x reference)
#include <cuda_runtime.h>
#include <cuda_bf16.h>

// STSEarlyFusionConcat: out (1, 2C, D, H, W) fp32
//   out[c,d,h,w]    = (w>=d) ? x[c,h,w]   : 0    for c in [0,C)
//   out[C+c,d,h,w]  = (w>=d) ? y[c,h,w-d] : 0    for c in [0,C)
// B=1, C=32, H=96, W=192, D=64.  HBM-write-bound: 302 MB out.
// R5: each thread owns 8 consecutive w (two float4) x 4 consecutive d.
//   x: 2 LDG.128 -> 8 masked STG.128 (1KB warp burst per plane)
//   y: 11 predicated scalar loads (y[b-3..b+7]) cover all 32 components

namespace {
constexpr int C   = 32;
constexpr int H   = 96;
constexpr int W   = 192;
constexpr int D   = 64;
constexpr int W8  = W / 8;                 // 24 float8 per row
constexpr int DQ  = D / 4;                 // 16
constexpr long long NTHREADS = (long long)(2 * C) * DQ * H * W8;  // 2,359,296
}

__global__ __launch_bounds__(256)
void stsef_kernel(const float* __restrict__ x,
                  const float* __restrict__ y,
                  float4* __restrict__ out)
{
    unsigned idx = blockIdx.x * blockDim.x + threadIdx.x;
    // idx = ((c2*DQ + dq)*H + h)*W8 + w8
    unsigned w8 = idx % W8;
    unsigned t  = idx / W8;
    unsigned h  = t % H;   t /= H;
    unsigned dq = t % DQ;  t /= DQ;
    unsigned c2 = t;                        // 0..63

    int w0 = (int)(w8 * 8);
    int d0 = (int)(dq * 4);

    // float4 index of first store: plane (c2,d0), row h, col w0/4
    size_t obase = (((size_t)(c2 * D + d0) * H) + h) * (W / 4) + (w8 * 2);
    const size_t dstr = (size_t)H * (W / 4);        // float4 stride per d

    if (c2 < C) {
        // cost_x: two aligned vector loads, 8 masked streaming stores
        const float4* xr = reinterpret_cast<const float4*>(x + ((c2 * H) + h) * W);
        float4 xa = __ldg(xr + w8 * 2);
        float4 xb = __ldg(xr + w8 * 2 + 1);
#pragma unroll
        for (int k = 0; k < 4; k++) {
            int dd = d0 + k;
            float4 va, vb;
            va.x = (w0 + 0 >= dd) ? xa.x : 0.0f;
            va.y = (w0 + 1 >= dd) ? xa.y : 0.0f;
            va.z = (w0 + 2 >= dd) ? xa.z : 0.0f;
            va.w = (w0 + 3 >= dd) ? xa.w : 0.0f;
            vb.x = (w0 + 4 >= dd) ? xb.x : 0.0f;
            vb.y = (w0 + 5 >= dd) ? xb.y : 0.0f;
            vb.z = (w0 + 6 >= dd) ? xb.z : 0.0f;
            vb.w = (w0 + 7 >= dd) ? xb.w : 0.0f;
            __stcs(out + obase + (size_t)k * dstr,     va);
            __stcs(out + obase + (size_t)k * dstr + 1, vb);
        }
    } else {
        // cost_y: 11 scalars y[b-3 .. b+7] (b = w0-d0) cover 8w x 4d windows.
        // component (j,k) = y[b + j - k] = tv[3 + j - k],  j:0..7, k:0..3
        const float* yr = y + (((c2 - C) * H) + h) * W;
        int b = w0 - d0;
        float tv[11];
#pragma unroll
        for (int i = 0; i < 11; i++) {
            int e = b - 3 + i;
            tv[i] = (e >= 0) ? __ldg(yr + e) : 0.0f;
        }
#pragma unroll
        for (int k = 0; k < 4; k++) {
            float4 va, vb;
            va.x = tv[3 - k];
            va.y = tv[4 - k];
            va.z = tv[5 - k];
            va.w = tv[6 - k];
            vb.x = tv[7 - k];
            vb.y = tv[8 - k];
            vb.z = tv[9 - k];
            vb.w = tv[10 - k];
            __stcs(out + obase + (size_t)k * dstr,     va);
            __stcs(out + obase + (size_t)k * dstr + 1, vb);
        }
    }
}

extern "C" void kernel_launch(void* const* d_in, const int* in_sizes, int n_in,
                              void* d_out, int out_size)
{
    const float* x = (const float*)d_in[0];
    const float* y = (const float*)d_in[1];
    float4* out = (float4*)d_out;

    const int threads = 256;
    const unsigned blocks = (unsigned)(NTHREADS / threads);  // 9,216
    stsef_kernel<<<blocks, threads>>>(x, y, out);
}

// round 6
// speedup vs baseline: 1.1443x; 1.1443x over previous
#include <cuda_runtime.h>
#include <cuda_bf16.h>
#include <cstdint>

// STSEarlyFusionConcat: out (1, 2C, D, H, W) fp32
//   out[c,d,h,w]    = (w>=d) ? x[c,h,w]   : 0    for c in [0,C)
//   out[C+c,d,h,w]  = (w>=d) ? y[c,h,w-d] : 0    for c in [0,C)
// B=1, C=32, H=96, W=192, D=64.  HBM-write-bound: 302 MB out.
// R6: stage 36KB output half-planes in SMEM, drain via cp.async.bulk
// (TMA bulk store) -> large sequential DRAM writes, no per-thread STG issue.

namespace {
constexpr int C   = 32;
constexpr int H   = 96;
constexpr int W   = 192;
constexpr int D   = 64;
constexpr int W4  = W / 4;                    // 48
constexpr int HR  = H / 2;                    // 48 rows per half-plane
constexpr int HALF4  = HR * W4;               // 2304 float4 = 36 KB
constexpr int HALF_F = HR * W;                // 9216 floats
constexpr int TPB = 256;
constexpr int KPT = HALF4 / TPB;              // 9 float4 per thread
constexpr int NBLOCKS = 2 * C * D * 2;        // 8192
}

__global__ __launch_bounds__(TPB)
void stsef_kernel(const float* __restrict__ x,
                  const float* __restrict__ y,
                  float* __restrict__ out)
{
    __shared__ float4 buf[HALF4];             // 36 KB staging

    unsigned bid  = blockIdx.x;
    unsigned half = bid & 1;
    unsigned pd   = bid >> 1;                 // plane = (c2, d)
    int      d    = (int)(pd & 63);
    unsigned c2   = pd >> 6;
    unsigned t    = threadIdx.x;

    if (c2 < C) {
        // cost_x half-plane: masked copy of x channel rows [half*HR, half*HR+HR)
        const float4* xp = reinterpret_cast<const float4*>(
            x + ((size_t)c2 * H + half * HR) * W);
#pragma unroll
        for (int k = 0; k < KPT; k++) {
            unsigned i  = t + k * TPB;
            int w0 = (int)(i % W4) * 4;
            float4 v = __ldg(xp + i);
            v.x = (w0 + 0 >= d) ? v.x : 0.0f;
            v.y = (w0 + 1 >= d) ? v.y : 0.0f;
            v.z = (w0 + 2 >= d) ? v.z : 0.0f;
            v.w = (w0 + 3 >= d) ? v.w : 0.0f;
            buf[i] = v;
        }
    } else {
        // cost_y half-plane: row-shifted y; load predicate == zero mask
        const float* yb = y + ((size_t)(c2 - C) * H + half * HR) * W;
#pragma unroll
        for (int k = 0; k < KPT; k++) {
            unsigned i  = t + k * TPB;
            unsigned h  = i / W4;
            int b0 = (int)(i % W4) * 4 - d;
            const float* row = yb + h * W;
            float4 v;
            v.x = (b0 + 0 >= 0) ? __ldg(row + b0 + 0) : 0.0f;
            v.y = (b0 + 1 >= 0) ? __ldg(row + b0 + 1) : 0.0f;
            v.z = (b0 + 2 >= 0) ? __ldg(row + b0 + 2) : 0.0f;
            v.w = (b0 + 3 >= 0) ? __ldg(row + b0 + 3) : 0.0f;
            buf[i] = v;
        }
    }

    __syncthreads();

    if (t == 0) {
        // order generic STS before async-proxy read, then bulk store
        asm volatile("fence.proxy.async.shared::cta;" ::: "memory");
        uint32_t saddr = (uint32_t)__cvta_generic_to_shared(buf);
        float* dst = out + (size_t)pd * (H * W) + (size_t)half * HALF_F;
        asm volatile(
            "cp.async.bulk.global.shared::cta.bulk_group [%0], [%1], %2;"
            :: "l"(dst), "r"(saddr), "n"(HALF4 * 16) : "memory");
        asm volatile("cp.async.bulk.commit_group;" ::: "memory");
        // must drain before block exit (SMEM reuse by next block)
        asm volatile("cp.async.bulk.wait_group.read 0;" ::: "memory");
    }
}

extern "C" void kernel_launch(void* const* d_in, const int* in_sizes, int n_in,
                              void* d_out, int out_size)
{
    const float* x = (const float*)d_in[0];
    const float* y = (const float*)d_in[1];
    float* out = (float*)d_out;

    stsef_kernel<<<NBLOCKS, TPB>>>(x, y, out);
}

// round 7
// speedup vs baseline: 1.5279x; 1.3352x over previous
#include <cuda_runtime.h>
#include <cuda_bf16.h>

// STSEarlyFusionConcat: out (1, 2C, D, H, W) fp32
//   out[c,d,h,w]    = (w>=d) ? x[c,h,w]   : 0    for c in [0,C)
//   out[C+c,d,h,w]  = (w>=d) ? y[c,h,w-d] : 0    for c in [0,C)
// B=1, C=32, H=96, W=192, D=64.  HBM-write-bound.
// R7 = R2 winning shape (4 d-values/thread, coalesced float4, load-batch ->
// 4 independent STG.128) with two changes:
//   (a) default .wb stores (not .cs): replayed launches overwrite the same
//       d_out; dirty lines retained in L2 from the previous launch absorb
//       part of the write traffic.
//   (b) c2 in a low digit of the index: x- and y-blocks co-resident.

namespace {
constexpr int C   = 32;
constexpr int H   = 96;
constexpr int W   = 192;
constexpr int D   = 64;
constexpr int W4  = W / 4;                 // 48
constexpr int DQ  = D / 4;                 // 16
constexpr long long NTHREADS = (long long)(2 * C) * DQ * H * W4;  // 4,718,592
}

__global__ __launch_bounds__(256)
void stsef_kernel(const float* __restrict__ x,
                  const float* __restrict__ y,
                  float4* __restrict__ out)
{
    unsigned idx = blockIdx.x * blockDim.x + threadIdx.x;
    // idx = ((dq*2C + c2)*H + h)*W4 + w4   (c2 below h -> x/y blocks interleave)
    unsigned w4 = idx % W4;
    unsigned t  = idx / W4;
    unsigned h  = t % H;   t /= H;
    unsigned c2 = t % (2 * C);  t /= (2 * C);
    unsigned dq = t;                        // 0..15

    int w0 = (int)(w4 * 4);
    int d0 = (int)(dq * 4);

    size_t obase = (((size_t)(c2 * D + d0) * H) + h) * W4 + w4;  // float4 index
    const size_t dstr = (size_t)H * W4;                          // stride per d

    if (c2 < C) {
        // cost_x: one aligned vector load, 4 masked stores (default .wb)
        const float4* xr = reinterpret_cast<const float4*>(x + ((c2 * H) + h) * W);
        float4 xv = __ldg(xr + w4);
#pragma unroll
        for (int k = 0; k < 4; k++) {
            int dd = d0 + k;
            float4 v;
            v.x = (w0 + 0 >= dd) ? xv.x : 0.0f;
            v.y = (w0 + 1 >= dd) ? xv.y : 0.0f;
            v.z = (w0 + 2 >= dd) ? xv.z : 0.0f;
            v.w = (w0 + 3 >= dd) ? xv.w : 0.0f;
            out[obase + (size_t)k * dstr] = v;
        }
    } else {
        // cost_y: 7 scalars y[b-3 .. b+3] (b = w0-d0) cover the 4 shifted windows.
        // Load predicate (e >= 0) doubles as the validity mask.
        const float* yr = y + (((c2 - C) * H) + h) * W;
        int b = w0 - d0;
        float tv[7];
#pragma unroll
        for (int i = 0; i < 7; i++) {
            int e = b - 3 + i;
            tv[i] = (e >= 0) ? __ldg(yr + e) : 0.0f;
        }
#pragma unroll
        for (int k = 0; k < 4; k++) {
            // component j of store k = y[b + j - k] = tv[3 + j - k]
            float4 v;
            v.x = tv[3 - k];
            v.y = tv[4 - k];
            v.z = tv[5 - k];
            v.w = tv[6 - k];
            out[obase + (size_t)k * dstr] = v;
        }
    }
}

extern "C" void kernel_launch(void* const* d_in, const int* in_sizes, int n_in,
                              void* d_out, int out_size)
{
    const float* x = (const float*)d_in[0];
    const float* y = (const float*)d_in[1];
    float4* out = (float4*)d_out;

    const int threads = 256;
    const unsigned blocks = (unsigned)(NTHREADS / threads);  // 18,432
    stsef_kernel<<<blocks, threads>>>(x, y, out);
}

// round 8
// speedup vs baseline: 1.7897x; 1.1713x over previous
#include <cuda_runtime.h>
#include <cuda_bf16.h>

// STSEarlyFusionConcat: out (1, 2C, D, H, W) fp32
//   out[c,d,h,w]    = (w>=d) ? x[c,h,w]   : 0    for c in [0,C)
//   out[C+c,d,h,w]  = (w>=d) ? y[c,h,w-d] : 0    for c in [0,C)
// B=1, C=32, H=96, W=192, D=64.
// R8 = R2 (4 d/thread, coalesced float4, .cs stores, c2-major) with the
// y-path's 7 scalar loads replaced by 2 predicated LDG.128:
//   b = 4*(w4 - dq) is 16B-aligned, so window y[b-3..b+3] ⊂ {f4[b-4], f4[b]};
//   predicates (b>=4, b>=0) are exactly the zero-masks. 28 -> 8 load
//   wavefronts per warp-iteration (L1TEX was the top in-kernel limiter).

namespace {
constexpr int C   = 32;
constexpr int H   = 96;
constexpr int W   = 192;
constexpr int D   = 64;
constexpr int W4  = W / 4;                 // 48
constexpr int DQ  = D / 4;                 // 16
constexpr long long NTHREADS = (long long)(2 * C) * DQ * H * W4;  // 4,718,592
}

__global__ __launch_bounds__(256)
void stsef_kernel(const float* __restrict__ x,
                  const float* __restrict__ y,
                  float4* __restrict__ out)
{
    unsigned idx = blockIdx.x * blockDim.x + threadIdx.x;
    // idx = ((c2*DQ + dq)*H + h)*W4 + w4
    unsigned w4 = idx % W4;
    unsigned t  = idx / W4;
    unsigned h  = t % H;   t /= H;
    unsigned dq = t % DQ;  t /= DQ;
    unsigned c2 = t;                        // 0..63

    int w0 = (int)(w4 * 4);
    int d0 = (int)(dq * 4);

    size_t obase = (((size_t)(c2 * D + d0) * H) + h) * W4 + w4;  // float4 index
    const size_t dstr = (size_t)H * W4;                          // stride per d

    if (c2 < C) {
        // cost_x: one aligned vector load, 4 masked streaming stores
        const float4* xr = reinterpret_cast<const float4*>(x + ((c2 * H) + h) * W);
        float4 xv = __ldg(xr + w4);
#pragma unroll
        for (int k = 0; k < 4; k++) {
            int dd = d0 + k;
            float4 v;
            v.x = (w0 + 0 >= dd) ? xv.x : 0.0f;
            v.y = (w0 + 1 >= dd) ? xv.y : 0.0f;
            v.z = (w0 + 2 >= dd) ? xv.z : 0.0f;
            v.w = (w0 + 3 >= dd) ? xv.w : 0.0f;
            __stcs(out + obase + (size_t)k * dstr, v);
        }
    } else {
        // cost_y: window y[b-3..b+3], b = w0-d0 = 4*(w4-dq) (16B-aligned).
        // Two predicated vector loads; predicate == zero mask.
        const float4* yr4 = reinterpret_cast<const float4*>(
            y + (((c2 - C) * H) + h) * W);
        int q = (int)w4 - (int)dq;          // b/4
        float4 A  = make_float4(0.f, 0.f, 0.f, 0.f);
        float4 Bv = make_float4(0.f, 0.f, 0.f, 0.f);
        if (q >= 1) A  = __ldg(yr4 + (q - 1));   // y[b-4 .. b-1]
        if (q >= 0) Bv = __ldg(yr4 + q);         // y[b   .. b+3]
        // tv[i] = y[b-3+i] (0 if OOB):
        float tv[7];
        tv[0] = A.y;  tv[1] = A.z;  tv[2] = A.w;
        tv[3] = Bv.x; tv[4] = Bv.y; tv[5] = Bv.z; tv[6] = Bv.w;
#pragma unroll
        for (int k = 0; k < 4; k++) {
            // component j of store k = y[b + j - k] = tv[3 + j - k]
            float4 v;
            v.x = tv[3 - k];
            v.y = tv[4 - k];
            v.z = tv[5 - k];
            v.w = tv[6 - k];
            __stcs(out + obase + (size_t)k * dstr, v);
        }
    }
}

extern "C" void kernel_launch(void* const* d_in, const int* in_sizes, int n_in,
                              void* d_out, int out_size)
{
    const float* x = (const float*)d_in[0];
    const float* y = (const float*)d_in[1];
    float4* out = (float4*)d_out;

    const int threads = 256;
    const unsigned blocks = (unsigned)(NTHREADS / threads);  // 18,432
    stsef_kernel<<<blocks, threads>>>(x, y, out);
}